// round 4
// baseline (speedup 1.0000x reference)
#include <cuda_runtime.h>
#include <cuda_bf16.h>

#define BATCH 8
#define SEQ   2048
#define DIM   512
#define DKK   64
#define SP    40   // smem pitch (bf16) for 32-wide k tiles
#define SP64  72   // smem pitch (bf16) for 64-wide k tiles
#define TPITCH 136 // vtrans smem pitch (272B = 17*16 -> uint4-aligned)

// ------------------------- device scratch (module-load allocated) ----------
__device__ __nv_bfloat16 g_Qh[BATCH * SEQ * DKK];
__device__ __nv_bfloat16 g_Ql[BATCH * SEQ * DKK];
__device__ __nv_bfloat16 g_Kh[BATCH * SEQ * DKK];
__device__ __nv_bfloat16 g_Kl[BATCH * SEQ * DKK];
__device__ __nv_bfloat16 g_Vh[BATCH * SEQ * DKK];
__device__ __nv_bfloat16 g_Vl[BATCH * SEQ * DKK];
__device__ __nv_bfloat16 g_Vth[BATCH * DKK * SEQ];   // V transposed [b][n][s]
__device__ __nv_bfloat16 g_Vtl[BATCH * DKK * SEQ];
__device__ float g_rowsum[64 * BATCH * SEQ];         // [chunk 64][b*S+row]
__device__ float g_inv[BATCH * SEQ];                 // 1/rowsum

// ------------------------- helpers -----------------------------------------
__device__ __forceinline__ void split2(float x0, float x1, unsigned &h, unsigned &l) {
    __nv_bfloat16 h0 = __float2bfloat16(x0);
    __nv_bfloat16 h1 = __float2bfloat16(x1);
    float r0 = x0 - __bfloat162float(h0);
    float r1 = x1 - __bfloat162float(h1);
    __nv_bfloat162 hv; hv.x = h0; hv.y = h1;
    __nv_bfloat162 lv; lv.x = __float2bfloat16(r0); lv.y = __float2bfloat16(r1);
    h = *reinterpret_cast<unsigned*>(&hv);
    l = *reinterpret_cast<unsigned*>(&lv);
}

__device__ __forceinline__ void mma16816(float* d, const unsigned* a, const unsigned* b) {
    asm volatile(
        "mma.sync.aligned.m16n8k16.row.col.f32.bf16.bf16.f32 "
        "{%0,%1,%2,%3},{%4,%5,%6,%7},{%8,%9},{%0,%1,%2,%3};"
        : "+f"(d[0]), "+f"(d[1]), "+f"(d[2]), "+f"(d[3])
        : "r"(a[0]), "r"(a[1]), "r"(a[2]), "r"(a[3]), "r"(b[0]), "r"(b[1]));
}

// ---------------------------------------------------------------------------
// Kernel 1: QKV projection via bf16-split MMA.
// ---------------------------------------------------------------------------
__global__ void __launch_bounds__(256) qkv_mma(const float* __restrict__ in,
                                               const float* __restrict__ Wq,
                                               const float* __restrict__ Wk,
                                               const float* __restrict__ Wv) {
    __shared__ __nv_bfloat16 sAh[128 * SP], sAl[128 * SP];
    __shared__ __nv_bfloat16 sBh[64 * SP],  sBl[64 * SP];

    const int m0    = blockIdx.x * 128;
    const int which = blockIdx.y;
    const float* W = (which == 0) ? Wq : (which == 1) ? Wk : Wv;
    __nv_bfloat16 *oh, *ol;
    if (which == 0)      { oh = g_Qh; ol = g_Ql; }
    else if (which == 1) { oh = g_Kh; ol = g_Kl; }
    else                 { oh = g_Vh; ol = g_Vl; }

    const int tid = threadIdx.x, lane = tid & 31, warp = tid >> 5;
    const int wr = warp >> 1, wc = warp & 1;
    const int gid = lane >> 2, tig = lane & 3;

    float acc[2][4][4] = {};

    for (int kc = 0; kc < 16; kc++) {
        const int k0 = kc * 32;
#pragma unroll
        for (int j = 0; j < 4; j++) {
            int idx = tid + j * 256;
            int r = idx >> 3, seg = idx & 7;
            float4 f = *(const float4*)&in[(size_t)(m0 + r) * DIM + k0 + seg * 4];
            unsigned h0, l0, h1, l1;
            split2(f.x, f.y, h0, l0);
            split2(f.z, f.w, h1, l1);
            *(unsigned*)&sAh[r * SP + seg * 4]     = h0;
            *(unsigned*)&sAh[r * SP + seg * 4 + 2] = h1;
            *(unsigned*)&sAl[r * SP + seg * 4]     = l0;
            *(unsigned*)&sAl[r * SP + seg * 4 + 2] = l1;
        }
#pragma unroll
        for (int j = 0; j < 8; j++) {
            int idx = tid + j * 256;
            int kk = idx >> 6, n = idx & 63;
            float v = W[(size_t)(k0 + kk) * DKK + n];
            __nv_bfloat16 h = __float2bfloat16(v);
            __nv_bfloat16 l = __float2bfloat16(v - __bfloat162float(h));
            sBh[n * SP + kk] = h;
            sBl[n * SP + kk] = l;
        }
        __syncthreads();

#pragma unroll
        for (int ks = 0; ks < 2; ks++) {
            const int kk = ks * 16;
            unsigned bh[4][2], bl[4][2];
#pragma unroll
            for (int nt = 0; nt < 4; nt++) {
                int n = wc * 32 + nt * 8 + gid;
                bh[nt][0] = *(unsigned*)&sBh[n * SP + kk + tig * 2];
                bh[nt][1] = *(unsigned*)&sBh[n * SP + kk + 8 + tig * 2];
                bl[nt][0] = *(unsigned*)&sBl[n * SP + kk + tig * 2];
                bl[nt][1] = *(unsigned*)&sBl[n * SP + kk + 8 + tig * 2];
            }
#pragma unroll
            for (int mt = 0; mt < 2; mt++) {
                int m = wr * 32 + mt * 16;
                unsigned ah[4], al[4];
                ah[0] = *(unsigned*)&sAh[(m + gid) * SP + kk + tig * 2];
                ah[1] = *(unsigned*)&sAh[(m + gid + 8) * SP + kk + tig * 2];
                ah[2] = *(unsigned*)&sAh[(m + gid) * SP + kk + 8 + tig * 2];
                ah[3] = *(unsigned*)&sAh[(m + gid + 8) * SP + kk + 8 + tig * 2];
                al[0] = *(unsigned*)&sAl[(m + gid) * SP + kk + tig * 2];
                al[1] = *(unsigned*)&sAl[(m + gid + 8) * SP + kk + tig * 2];
                al[2] = *(unsigned*)&sAl[(m + gid) * SP + kk + 8 + tig * 2];
                al[3] = *(unsigned*)&sAl[(m + gid + 8) * SP + kk + 8 + tig * 2];
#pragma unroll
                for (int nt = 0; nt < 4; nt++) {
                    mma16816(acc[mt][nt], ah, bh[nt]);
                    mma16816(acc[mt][nt], ah, bl[nt]);
                    mma16816(acc[mt][nt], al, bh[nt]);
                }
            }
        }
        __syncthreads();
    }

#pragma unroll
    for (int mt = 0; mt < 2; mt++)
#pragma unroll
        for (int nt = 0; nt < 4; nt++) {
            int row = m0 + wr * 32 + mt * 16 + gid;
            int col = wc * 32 + nt * 8 + tig * 2;
            size_t o = (size_t)row * DKK + col;
            unsigned h, l;
            split2(acc[mt][nt][0], acc[mt][nt][1], h, l);
            *reinterpret_cast<unsigned*>(&oh[o]) = h;
            *reinterpret_cast<unsigned*>(&ol[o]) = l;
            split2(acc[mt][nt][2], acc[mt][nt][3], h, l);
            *reinterpret_cast<unsigned*>(&oh[o + (size_t)8 * DKK]) = h;
            *reinterpret_cast<unsigned*>(&ol[o + (size_t)8 * DKK]) = l;
        }
}

// ---------------------------------------------------------------------------
// Kernel 1b: transpose V planes: g_Vh[b][s][n] -> g_Vth[b][n][s]
// ---------------------------------------------------------------------------
__global__ void __launch_bounds__(256) vtrans() {
    __shared__ __nv_bfloat16 st[64 * TPITCH];
    const int b  = blockIdx.y;
    const int s0 = blockIdx.x * 128;
    const int tid = threadIdx.x;

    for (int plane = 0; plane < 2; plane++) {
        const __nv_bfloat16* src = (plane ? g_Vl : g_Vh) + (size_t)b * SEQ * DKK;
        __nv_bfloat16*       dst = (plane ? g_Vtl : g_Vth) + (size_t)b * DKK * SEQ;
#pragma unroll
        for (int j = 0; j < 4; j++) {
            int idx = tid + j * 256;             // 0..1023
            int sl = idx >> 3, c8 = idx & 7;
            uint4 v = *(const uint4*)&src[(size_t)(s0 + sl) * DKK + c8 * 8];
            __nv_bfloat16 tmp[8];
            *(uint4*)tmp = v;
#pragma unroll
            for (int i = 0; i < 8; i++)
                st[(c8 * 8 + i) * TPITCH + sl] = tmp[i];
        }
        __syncthreads();
#pragma unroll
        for (int j = 0; j < 4; j++) {
            int idx = tid + j * 256;
            int n = idx >> 4, k8 = idx & 15;
            *(uint4*)&dst[(size_t)n * SEQ + s0 + k8 * 8] = *(uint4*)&st[n * TPITCH + k8 * 8];
        }
        __syncthreads();
    }
}

// ---------------------------------------------------------------------------
// Kernel 2: unnormalized exp'd scores = exp(0.125 * Q K^T), plus partial
// row sums to g_rowsum. Block 128x128, 8 warps (2x4), warp tile 64x32.
// ---------------------------------------------------------------------------
__global__ void __launch_bounds__(256) scores_exp(float* __restrict__ weights) {
    __shared__ __nv_bfloat16 sQh[128 * SP], sQl[128 * SP];
    __shared__ __nv_bfloat16 sKh[128 * SP], sKl[128 * SP];

    const int b  = blockIdx.z;
    const int m0 = blockIdx.y * 128;
    const int n0 = blockIdx.x * 128;
    const __nv_bfloat16* qh = g_Qh + (size_t)b * SEQ * DKK;
    const __nv_bfloat16* ql = g_Ql + (size_t)b * SEQ * DKK;
    const __nv_bfloat16* kh = g_Kh + (size_t)b * SEQ * DKK;
    const __nv_bfloat16* kl = g_Kl + (size_t)b * SEQ * DKK;

    const int tid = threadIdx.x, lane = tid & 31, warp = tid >> 5;
    const int wr = warp >> 2, wc = warp & 3;
    const int gid = lane >> 2, tig = lane & 3;

    float acc[4][4][4] = {};

    for (int kc = 0; kc < 2; kc++) {
        const int k0 = kc * 32;
#pragma unroll
        for (int j = 0; j < 2; j++) {
            int idx = tid + j * 256;
            int r = idx >> 2, seg = idx & 3;
            *(uint4*)&sQh[r * SP + seg * 8] = *(const uint4*)&qh[(size_t)(m0 + r) * DKK + k0 + seg * 8];
            *(uint4*)&sQl[r * SP + seg * 8] = *(const uint4*)&ql[(size_t)(m0 + r) * DKK + k0 + seg * 8];
            *(uint4*)&sKh[r * SP + seg * 8] = *(const uint4*)&kh[(size_t)(n0 + r) * DKK + k0 + seg * 8];
            *(uint4*)&sKl[r * SP + seg * 8] = *(const uint4*)&kl[(size_t)(n0 + r) * DKK + k0 + seg * 8];
        }
        __syncthreads();

#pragma unroll
        for (int ks = 0; ks < 2; ks++) {
            const int kk = ks * 16;
            unsigned bh[4][2], bl[4][2];
#pragma unroll
            for (int nt = 0; nt < 4; nt++) {
                int n = wc * 32 + nt * 8 + gid;
                bh[nt][0] = *(unsigned*)&sKh[n * SP + kk + tig * 2];
                bh[nt][1] = *(unsigned*)&sKh[n * SP + kk + 8 + tig * 2];
                bl[nt][0] = *(unsigned*)&sKl[n * SP + kk + tig * 2];
                bl[nt][1] = *(unsigned*)&sKl[n * SP + kk + 8 + tig * 2];
            }
#pragma unroll
            for (int mt = 0; mt < 4; mt++) {
                int m = wr * 64 + mt * 16;
                unsigned ah[4], al[4];
                ah[0] = *(unsigned*)&sQh[(m + gid) * SP + kk + tig * 2];
                ah[1] = *(unsigned*)&sQh[(m + gid + 8) * SP + kk + tig * 2];
                ah[2] = *(unsigned*)&sQh[(m + gid) * SP + kk + 8 + tig * 2];
                ah[3] = *(unsigned*)&sQh[(m + gid + 8) * SP + kk + 8 + tig * 2];
                al[0] = *(unsigned*)&sQl[(m + gid) * SP + kk + tig * 2];
                al[1] = *(unsigned*)&sQl[(m + gid + 8) * SP + kk + tig * 2];
                al[2] = *(unsigned*)&sQl[(m + gid) * SP + kk + 8 + tig * 2];
                al[3] = *(unsigned*)&sQl[(m + gid + 8) * SP + kk + 8 + tig * 2];
#pragma unroll
                for (int nt = 0; nt < 4; nt++) {
                    mma16816(acc[mt][nt], ah, bh[nt]);
                    mma16816(acc[mt][nt], ah, bl[nt]);
                    mma16816(acc[mt][nt], al, bh[nt]);
                }
            }
        }
        __syncthreads();
    }

    // exp in place (no max subtraction: |score| <~ 8, fp32-safe)
#pragma unroll
    for (int mt = 0; mt < 4; mt++)
#pragma unroll
        for (int nt = 0; nt < 4; nt++)
#pragma unroll
            for (int j = 0; j < 4; j++)
                acc[mt][nt][j] = __expf(acc[mt][nt][j] * 0.125f);

    // partial row sums over this warp's 32 columns
#pragma unroll
    for (int mt = 0; mt < 4; mt++) {
        float s0 = 0.f, s1 = 0.f;
#pragma unroll
        for (int nt = 0; nt < 4; nt++) {
            s0 += acc[mt][nt][0] + acc[mt][nt][1];
            s1 += acc[mt][nt][2] + acc[mt][nt][3];
        }
        s0 += __shfl_xor_sync(0xffffffffu, s0, 1);
        s0 += __shfl_xor_sync(0xffffffffu, s0, 2);
        s1 += __shfl_xor_sync(0xffffffffu, s1, 1);
        s1 += __shfl_xor_sync(0xffffffffu, s1, 2);
        if (tig == 0) {
            int row = m0 + wr * 64 + mt * 16 + gid;
            size_t base = (size_t)(blockIdx.x * 4 + wc) * (BATCH * SEQ) + (size_t)b * SEQ + row;
            g_rowsum[base]     = s0;
            g_rowsum[base + 8] = s1;
        }
    }

    float* outb = weights + (size_t)b * SEQ * SEQ;
#pragma unroll
    for (int mt = 0; mt < 4; mt++)
#pragma unroll
        for (int nt = 0; nt < 4; nt++) {
            int row = m0 + wr * 64 + mt * 16 + gid;
            int col = n0 + wc * 32 + nt * 8 + tig * 2;
            float2 v0 = { acc[mt][nt][0], acc[mt][nt][1] };
            float2 v1 = { acc[mt][nt][2], acc[mt][nt][3] };
            *(float2*)&outb[(size_t)row * SEQ + col]       = v0;
            *(float2*)&outb[(size_t)(row + 8) * SEQ + col] = v1;
        }
}

// ---------------------------------------------------------------------------
// Kernel 3: reduce 64 partial sums per row -> 1/sum
// ---------------------------------------------------------------------------
__global__ void __launch_bounds__(256) rowinv() {
    int i = blockIdx.x * 256 + threadIdx.x;   // 0 .. 16383
    float s = 0.f;
#pragma unroll
    for (int c = 0; c < 64; c++)
        s += g_rowsum[(size_t)c * (BATCH * SEQ) + i];
    g_inv[i] = 1.0f / s;
}

// ---------------------------------------------------------------------------
// Kernel 4: fused normalize + attend.
// Reads unnormalized exp weights, multiplies by inv[row], writes normalized
// weights back in place, bf16-splits into smem, MMAs with V^T.
// Block: 64 q-rows x 64 (DK), 8 warps (4x2), warp tile 16x32, S chunks of 64.
// ---------------------------------------------------------------------------
__global__ void __launch_bounds__(256) attend_norm(float* __restrict__ weights,
                                                   float* __restrict__ attended) {
    __shared__ __nv_bfloat16 sWh[64 * SP64], sWl[64 * SP64];
    __shared__ __nv_bfloat16 sVh[64 * SP64], sVl[64 * SP64];

    const int b  = blockIdx.y;
    const int m0 = blockIdx.x * 64;
    float* wb = weights + (size_t)b * SEQ * SEQ;
    const __nv_bfloat16* vth = g_Vth + (size_t)b * DKK * SEQ;
    const __nv_bfloat16* vtl = g_Vtl + (size_t)b * DKK * SEQ;
    const float* inv = g_inv + b * SEQ;

    const int tid = threadIdx.x, lane = tid & 31, warp = tid >> 5;
    const int wr = warp >> 1, wc = warp & 1;     // rows wr*16, cols wc*32
    const int gid = lane >> 2, tig = lane & 3;

    float acc[4][4] = {};

    for (int s0 = 0; s0 < SEQ; s0 += 64) {
        // stage W 64x64: read fp32, normalize, write back, split to smem
#pragma unroll
        for (int j = 0; j < 4; j++) {
            int idx = tid + j * 256;             // 0..1023
            int r = idx >> 4, c4 = idx & 15;     // cols c4*4
            size_t go = (size_t)(m0 + r) * SEQ + s0 + c4 * 4;
            float4 f = *(const float4*)&wb[go];
            float iv = inv[m0 + r];
            f.x *= iv; f.y *= iv; f.z *= iv; f.w *= iv;
            *(float4*)&wb[go] = f;
            unsigned h0, l0, h1, l1;
            split2(f.x, f.y, h0, l0);
            split2(f.z, f.w, h1, l1);
            *(unsigned*)&sWh[r * SP64 + c4 * 4]     = h0;
            *(unsigned*)&sWh[r * SP64 + c4 * 4 + 2] = h1;
            *(unsigned*)&sWl[r * SP64 + c4 * 4]     = l0;
            *(unsigned*)&sWl[r * SP64 + c4 * 4 + 2] = l1;
        }
        // stage V^T 64n x 64k (coalesced uint4)
#pragma unroll
        for (int j = 0; j < 2; j++) {
            int idx = tid + j * 256;             // 0..511
            int n = idx >> 3, k8 = idx & 7;
            *(uint4*)&sVh[n * SP64 + k8 * 8] = *(const uint4*)&vth[(size_t)n * SEQ + s0 + k8 * 8];
            *(uint4*)&sVl[n * SP64 + k8 * 8] = *(const uint4*)&vtl[(size_t)n * SEQ + s0 + k8 * 8];
        }
        __syncthreads();

#pragma unroll
        for (int ks = 0; ks < 4; ks++) {
            const int kk = ks * 16;
            const int m = wr * 16;
            unsigned ah[4], al[4];
            ah[0] = *(unsigned*)&sWh[(m + gid) * SP64 + kk + tig * 2];
            ah[1] = *(unsigned*)&sWh[(m + gid + 8) * SP64 + kk + tig * 2];
            ah[2] = *(unsigned*)&sWh[(m + gid) * SP64 + kk + 8 + tig * 2];
            ah[3] = *(unsigned*)&sWh[(m + gid + 8) * SP64 + kk + 8 + tig * 2];
            al[0] = *(unsigned*)&sWl[(m + gid) * SP64 + kk + tig * 2];
            al[1] = *(unsigned*)&sWl[(m + gid + 8) * SP64 + kk + tig * 2];
            al[2] = *(unsigned*)&sWl[(m + gid) * SP64 + kk + 8 + tig * 2];
            al[3] = *(unsigned*)&sWl[(m + gid + 8) * SP64 + kk + 8 + tig * 2];
#pragma unroll
            for (int nt = 0; nt < 4; nt++) {
                int n = wc * 32 + nt * 8 + gid;
                unsigned bh[2], bl[2];
                bh[0] = *(unsigned*)&sVh[n * SP64 + kk + tig * 2];
                bh[1] = *(unsigned*)&sVh[n * SP64 + kk + 8 + tig * 2];
                bl[0] = *(unsigned*)&sVl[n * SP64 + kk + tig * 2];
                bl[1] = *(unsigned*)&sVl[n * SP64 + kk + 8 + tig * 2];
                mma16816(acc[nt], ah, bh);
                mma16816(acc[nt], ah, bl);
                mma16816(acc[nt], al, bh);
            }
        }
        __syncthreads();
    }

#pragma unroll
    for (int nt = 0; nt < 4; nt++) {
        int row = m0 + wr * 16 + gid;
        int col = wc * 32 + nt * 8 + tig * 2;
        float2 v0 = { acc[nt][0], acc[nt][1] };
        float2 v1 = { acc[nt][2], acc[nt][3] };
        *(float2*)&attended[((size_t)b * SEQ + row) * DKK + col]     = v0;
        *(float2*)&attended[((size_t)b * SEQ + row + 8) * DKK + col] = v1;
    }
}

// ---------------------------------------------------------------------------
extern "C" void kernel_launch(void* const* d_in, const int* in_sizes, int n_in,
                              void* d_out, int out_size) {
    const float* in = (const float*)d_in[0];
    const float* Wq = (const float*)d_in[1];
    const float* Wk = (const float*)d_in[2];
    const float* Wv = (const float*)d_in[3];

    float* out      = (float*)d_out;
    float* attended = out;                               // [B,S,DK]
    float* weights  = out + (size_t)BATCH * SEQ * DKK;   // [B,S,S]

    // 1) QKV projection
    dim3 g1(SEQ * BATCH / 128, 3);
    qkv_mma<<<g1, 256>>>(in, Wq, Wk, Wv);

    // 1b) transpose V
    dim3 gt(SEQ / 128, BATCH);
    vtrans<<<gt, 256>>>();

    // 2) unnormalized exp'd scores + partial row sums
    dim3 g2(SEQ / 128, SEQ / 128, BATCH);
    scores_exp<<<g2, 256>>>(weights);

    // 3) 1/rowsum
    rowinv<<<(BATCH * SEQ) / 256, 256>>>();

    // 4) fused normalize + attend
    dim3 g4(SEQ / 64, BATCH);
    attend_norm<<<g4, 256>>>(weights, attended);
}

// round 5
// speedup vs baseline: 1.1785x; 1.1785x over previous
#include <cuda_runtime.h>
#include <cuda_bf16.h>

#define BATCH 8
#define SEQ   2048
#define DIM   512
#define DKK   64
#define SP    40    // smem pitch (bf16), qkv staging
#define SPK   72    // pitch for k=64 operand tiles (144B = 9*16)
#define SPP   136   // pitch for k=128 operand tiles (272B = 17*16)
#define TPITCH 136  // vtrans smem pitch
#define BM    64    // q rows per block
#define BS    128   // s chunk

// ------------------------- device scratch (module-load allocated) ----------
__device__ __nv_bfloat16 g_Qh[BATCH * SEQ * DKK];
__device__ __nv_bfloat16 g_Ql[BATCH * SEQ * DKK];
__device__ __nv_bfloat16 g_Kh[BATCH * SEQ * DKK];
__device__ __nv_bfloat16 g_Kl[BATCH * SEQ * DKK];
__device__ __nv_bfloat16 g_Vh[BATCH * SEQ * DKK];
__device__ __nv_bfloat16 g_Vl[BATCH * SEQ * DKK];
__device__ __nv_bfloat16 g_Vth[BATCH * DKK * SEQ];   // V transposed [b][n][s]
__device__ __nv_bfloat16 g_Vtl[BATCH * DKK * SEQ];
__device__ float g_inv[BATCH * SEQ];                 // 1/rowsum

// ------------------------- helpers -----------------------------------------
__device__ __forceinline__ void split2(float x0, float x1, unsigned &h, unsigned &l) {
    __nv_bfloat16 h0 = __float2bfloat16(x0);
    __nv_bfloat16 h1 = __float2bfloat16(x1);
    float r0 = x0 - __bfloat162float(h0);
    float r1 = x1 - __bfloat162float(h1);
    __nv_bfloat162 hv; hv.x = h0; hv.y = h1;
    __nv_bfloat162 lv; lv.x = __float2bfloat16(r0); lv.y = __float2bfloat16(r1);
    h = *reinterpret_cast<unsigned*>(&hv);
    l = *reinterpret_cast<unsigned*>(&lv);
}

__device__ __forceinline__ void mma16816(float* d, const unsigned* a, const unsigned* b) {
    asm volatile(
        "mma.sync.aligned.m16n8k16.row.col.f32.bf16.bf16.f32 "
        "{%0,%1,%2,%3},{%4,%5,%6,%7},{%8,%9},{%0,%1,%2,%3};"
        : "+f"(d[0]), "+f"(d[1]), "+f"(d[2]), "+f"(d[3])
        : "r"(a[0]), "r"(a[1]), "r"(a[2]), "r"(a[3]), "r"(b[0]), "r"(b[1]));
}

// ---------------------------------------------------------------------------
// Kernel 1: QKV projection via bf16-split MMA. (proven in R2/R4)
// ---------------------------------------------------------------------------
__global__ void __launch_bounds__(256) qkv_mma(const float* __restrict__ in,
                                               const float* __restrict__ Wq,
                                               const float* __restrict__ Wk,
                                               const float* __restrict__ Wv) {
    __shared__ __nv_bfloat16 sAh[128 * SP], sAl[128 * SP];
    __shared__ __nv_bfloat16 sBh[64 * SP],  sBl[64 * SP];

    const int m0    = blockIdx.x * 128;
    const int which = blockIdx.y;
    const float* W = (which == 0) ? Wq : (which == 1) ? Wk : Wv;
    __nv_bfloat16 *oh, *ol;
    if (which == 0)      { oh = g_Qh; ol = g_Ql; }
    else if (which == 1) { oh = g_Kh; ol = g_Kl; }
    else                 { oh = g_Vh; ol = g_Vl; }

    const int tid = threadIdx.x, lane = tid & 31, warp = tid >> 5;
    const int wr = warp >> 1, wc = warp & 1;
    const int gid = lane >> 2, tig = lane & 3;

    float acc[2][4][4] = {};

    for (int kc = 0; kc < 16; kc++) {
        const int k0 = kc * 32;
#pragma unroll
        for (int j = 0; j < 4; j++) {
            int idx = tid + j * 256;
            int r = idx >> 3, seg = idx & 7;
            float4 f = *(const float4*)&in[(size_t)(m0 + r) * DIM + k0 + seg * 4];
            unsigned h0, l0, h1, l1;
            split2(f.x, f.y, h0, l0);
            split2(f.z, f.w, h1, l1);
            *(unsigned*)&sAh[r * SP + seg * 4]     = h0;
            *(unsigned*)&sAh[r * SP + seg * 4 + 2] = h1;
            *(unsigned*)&sAl[r * SP + seg * 4]     = l0;
            *(unsigned*)&sAl[r * SP + seg * 4 + 2] = l1;
        }
#pragma unroll
        for (int j = 0; j < 8; j++) {
            int idx = tid + j * 256;
            int kk = idx >> 6, n = idx & 63;
            float v = W[(size_t)(k0 + kk) * DKK + n];
            __nv_bfloat16 h = __float2bfloat16(v);
            __nv_bfloat16 l = __float2bfloat16(v - __bfloat162float(h));
            sBh[n * SP + kk] = h;
            sBl[n * SP + kk] = l;
        }
        __syncthreads();

#pragma unroll
        for (int ks = 0; ks < 2; ks++) {
            const int kk = ks * 16;
            unsigned bh[4][2], bl[4][2];
#pragma unroll
            for (int nt = 0; nt < 4; nt++) {
                int n = wc * 32 + nt * 8 + gid;
                bh[nt][0] = *(unsigned*)&sBh[n * SP + kk + tig * 2];
                bh[nt][1] = *(unsigned*)&sBh[n * SP + kk + 8 + tig * 2];
                bl[nt][0] = *(unsigned*)&sBl[n * SP + kk + tig * 2];
                bl[nt][1] = *(unsigned*)&sBl[n * SP + kk + 8 + tig * 2];
            }
#pragma unroll
            for (int mt = 0; mt < 2; mt++) {
                int m = wr * 32 + mt * 16;
                unsigned ah[4], al[4];
                ah[0] = *(unsigned*)&sAh[(m + gid) * SP + kk + tig * 2];
                ah[1] = *(unsigned*)&sAh[(m + gid + 8) * SP + kk + tig * 2];
                ah[2] = *(unsigned*)&sAh[(m + gid) * SP + kk + 8 + tig * 2];
                ah[3] = *(unsigned*)&sAh[(m + gid + 8) * SP + kk + 8 + tig * 2];
                al[0] = *(unsigned*)&sAl[(m + gid) * SP + kk + tig * 2];
                al[1] = *(unsigned*)&sAl[(m + gid + 8) * SP + kk + tig * 2];
                al[2] = *(unsigned*)&sAl[(m + gid) * SP + kk + 8 + tig * 2];
                al[3] = *(unsigned*)&sAl[(m + gid + 8) * SP + kk + 8 + tig * 2];
#pragma unroll
                for (int nt = 0; nt < 4; nt++) {
                    mma16816(acc[mt][nt], ah, bh[nt]);
                    mma16816(acc[mt][nt], ah, bl[nt]);
                    mma16816(acc[mt][nt], al, bh[nt]);
                }
            }
        }
        __syncthreads();
    }

#pragma unroll
    for (int mt = 0; mt < 2; mt++)
#pragma unroll
        for (int nt = 0; nt < 4; nt++) {
            int row = m0 + wr * 32 + mt * 16 + gid;
            int col = wc * 32 + nt * 8 + tig * 2;
            size_t o = (size_t)row * DKK + col;
            unsigned h, l;
            split2(acc[mt][nt][0], acc[mt][nt][1], h, l);
            *reinterpret_cast<unsigned*>(&oh[o]) = h;
            *reinterpret_cast<unsigned*>(&ol[o]) = l;
            split2(acc[mt][nt][2], acc[mt][nt][3], h, l);
            *reinterpret_cast<unsigned*>(&oh[o + (size_t)8 * DKK]) = h;
            *reinterpret_cast<unsigned*>(&ol[o + (size_t)8 * DKK]) = l;
        }
}

// ---------------------------------------------------------------------------
// Kernel 1b: transpose V planes (fixed TPITCH=136 from R4, passed)
// ---------------------------------------------------------------------------
__global__ void __launch_bounds__(256) vtrans() {
    __shared__ __nv_bfloat16 st[64 * TPITCH];
    const int b  = blockIdx.y;
    const int s0 = blockIdx.x * 128;
    const int tid = threadIdx.x;

    for (int plane = 0; plane < 2; plane++) {
        const __nv_bfloat16* src = (plane ? g_Vl : g_Vh) + (size_t)b * SEQ * DKK;
        __nv_bfloat16*       dst = (plane ? g_Vtl : g_Vth) + (size_t)b * DKK * SEQ;
#pragma unroll
        for (int j = 0; j < 4; j++) {
            int idx = tid + j * 256;
            int sl = idx >> 3, c8 = idx & 7;
            uint4 v = *(const uint4*)&src[(size_t)(s0 + sl) * DKK + c8 * 8];
            __nv_bfloat16 tmp[8];
            *(uint4*)tmp = v;
#pragma unroll
            for (int i = 0; i < 8; i++)
                st[(c8 * 8 + i) * TPITCH + sl] = tmp[i];
        }
        __syncthreads();
#pragma unroll
        for (int j = 0; j < 4; j++) {
            int idx = tid + j * 256;
            int n = idx >> 4, k8 = idx & 15;
            *(uint4*)&dst[(size_t)n * SEQ + s0 + k8 * 8] = *(uint4*)&st[n * TPITCH + k8 * 8];
        }
        __syncthreads();
    }
}

// ---------------------------------------------------------------------------
// Kernel 2: fused flash-style attention.
// Per block: 64 q-rows. Loop S in 128-chunks:
//   MMA1 Q·K^T -> exp (registers) -> rowsum (registers) -> write unnormalized
//   exp to weights (write-only) -> split to smem P (reuses K smem) -> MMA2 P·V^T.
// End: reduce rowsums, write g_inv, normalize attended in registers, store.
// ---------------------------------------------------------------------------
__global__ void __launch_bounds__(256, 2) fused_attn(float* __restrict__ weights,
                                                     float* __restrict__ attended) {
    extern __shared__ __nv_bfloat16 sm[];
    __nv_bfloat16* sQh = sm;              // 64*SPK  = 4608
    __nv_bfloat16* sQl = sm + 4608;
    __nv_bfloat16* sKh = sm + 9216;       // 128*SPK = 9216 (reused as P: 64*SPP=8704)
    __nv_bfloat16* sKl = sm + 18432;
    __nv_bfloat16* sVh = sm + 27648;      // 64*SPP  = 8704
    __nv_bfloat16* sVl = sm + 36352;      // ends at 45056 elems (90112 B)
    float* rsum = (float*)(sm + 45056);   // 64 floats

    const int b  = blockIdx.y;
    const int m0 = blockIdx.x * BM;
    const __nv_bfloat16* qh  = g_Qh  + (size_t)b * SEQ * DKK;
    const __nv_bfloat16* ql  = g_Ql  + (size_t)b * SEQ * DKK;
    const __nv_bfloat16* kh  = g_Kh  + (size_t)b * SEQ * DKK;
    const __nv_bfloat16* kl  = g_Kl  + (size_t)b * SEQ * DKK;
    const __nv_bfloat16* vth = g_Vth + (size_t)b * DKK * SEQ;
    const __nv_bfloat16* vtl = g_Vtl + (size_t)b * DKK * SEQ;
    float* outb = weights + (size_t)b * SEQ * SEQ;

    const int tid = threadIdx.x, lane = tid & 31, warp = tid >> 5;
    const int wr = warp >> 1, wc = warp & 1;        // 4 m-warps x 2 n-warps
    const int gid = lane >> 2, tig = lane & 3;
    const int m = wr * 16;

    // stage Q once (64 x 64, both planes)
#pragma unroll
    for (int j = 0; j < 2; j++) {
        int idx = tid + j * 256;                    // 0..511
        int r = idx >> 3, c8 = idx & 7;
        *(uint4*)&sQh[r * SPK + c8 * 8] = *(const uint4*)&qh[(size_t)(m0 + r) * DKK + c8 * 8];
        *(uint4*)&sQl[r * SPK + c8 * 8] = *(const uint4*)&ql[(size_t)(m0 + r) * DKK + c8 * 8];
    }
    if (tid < 64) rsum[tid] = 0.f;

    float rs0 = 0.f, rs1 = 0.f;
    float acc2[4][4] = {};

    for (int s0 = 0; s0 < SEQ; s0 += BS) {
        // stage K chunk 128 x 64 (both planes)
#pragma unroll
        for (int j = 0; j < 4; j++) {
            int idx = tid + j * 256;                // 0..1023
            int r = idx >> 3, c8 = idx & 7;
            *(uint4*)&sKh[r * SPK + c8 * 8] = *(const uint4*)&kh[(size_t)(s0 + r) * DKK + c8 * 8];
            *(uint4*)&sKl[r * SPK + c8 * 8] = *(const uint4*)&kl[(size_t)(s0 + r) * DKK + c8 * 8];
        }
        // stage V^T chunk 64 x 128 (both planes)
#pragma unroll
        for (int j = 0; j < 4; j++) {
            int idx = tid + j * 256;                // 0..1023
            int n = idx >> 4, k8 = idx & 15;
            *(uint4*)&sVh[n * SPP + k8 * 8] = *(const uint4*)&vth[(size_t)n * SEQ + s0 + k8 * 8];
            *(uint4*)&sVl[n * SPP + k8 * 8] = *(const uint4*)&vtl[(size_t)n * SEQ + s0 + k8 * 8];
        }
        __syncthreads();

        // ---- MMA1: C1[64 x 128] = Q(64x64) . K^T ----
        float acc1[8][4] = {};
#pragma unroll
        for (int ks = 0; ks < 4; ks++) {
            const int kk = ks * 16;
            unsigned ah[4], al[4];
            ah[0] = *(unsigned*)&sQh[(m + gid) * SPK + kk + tig * 2];
            ah[1] = *(unsigned*)&sQh[(m + gid + 8) * SPK + kk + tig * 2];
            ah[2] = *(unsigned*)&sQh[(m + gid) * SPK + kk + 8 + tig * 2];
            ah[3] = *(unsigned*)&sQh[(m + gid + 8) * SPK + kk + 8 + tig * 2];
            al[0] = *(unsigned*)&sQl[(m + gid) * SPK + kk + tig * 2];
            al[1] = *(unsigned*)&sQl[(m + gid + 8) * SPK + kk + tig * 2];
            al[2] = *(unsigned*)&sQl[(m + gid) * SPK + kk + 8 + tig * 2];
            al[3] = *(unsigned*)&sQl[(m + gid + 8) * SPK + kk + 8 + tig * 2];
#pragma unroll
            for (int nt = 0; nt < 8; nt++) {
                int n = wc * 64 + nt * 8 + gid;
                unsigned bh[2], bl[2];
                bh[0] = *(unsigned*)&sKh[n * SPK + kk + tig * 2];
                bh[1] = *(unsigned*)&sKh[n * SPK + kk + 8 + tig * 2];
                bl[0] = *(unsigned*)&sKl[n * SPK + kk + tig * 2];
                bl[1] = *(unsigned*)&sKl[n * SPK + kk + 8 + tig * 2];
                mma16816(acc1[nt], ah, bh);
                mma16816(acc1[nt], ah, bl);
                mma16816(acc1[nt], al, bh);
            }
        }
        __syncthreads();   // all MMA1 reads of K done before P overwrites it

        // ---- exp, rowsum, write unnormalized weights, store P ----
        __nv_bfloat16* sPh = sKh;   // reuse (8704 <= 9216)
        __nv_bfloat16* sPl = sKl;
        const int r0 = m0 + m + gid, r1 = r0 + 8;
#pragma unroll
        for (int nt = 0; nt < 8; nt++) {
            int col = wc * 64 + nt * 8 + tig * 2;
            float e0 = __expf(acc1[nt][0] * 0.125f);
            float e1 = __expf(acc1[nt][1] * 0.125f);
            float e2 = __expf(acc1[nt][2] * 0.125f);
            float e3 = __expf(acc1[nt][3] * 0.125f);
            rs0 += e0 + e1;
            rs1 += e2 + e3;
            float2 w0 = {e0, e1}, w1 = {e2, e3};
            *(float2*)&outb[(size_t)r0 * SEQ + s0 + col] = w0;
            *(float2*)&outb[(size_t)r1 * SEQ + s0 + col] = w1;
            unsigned h, l;
            split2(e0, e1, h, l);
            *(unsigned*)&sPh[(m + gid) * SPP + col] = h;
            *(unsigned*)&sPl[(m + gid) * SPP + col] = l;
            split2(e2, e3, h, l);
            *(unsigned*)&sPh[(m + gid + 8) * SPP + col] = h;
            *(unsigned*)&sPl[(m + gid + 8) * SPP + col] = l;
        }
        __syncthreads();   // P complete

        // ---- MMA2: attended[64 x 64] += P(64x128) . V^T ----
#pragma unroll
        for (int ks = 0; ks < 8; ks++) {
            const int kk = ks * 16;
            unsigned ah[4], al[4];
            ah[0] = *(unsigned*)&sPh[(m + gid) * SPP + kk + tig * 2];
            ah[1] = *(unsigned*)&sPh[(m + gid + 8) * SPP + kk + tig * 2];
            ah[2] = *(unsigned*)&sPh[(m + gid) * SPP + kk + 8 + tig * 2];
            ah[3] = *(unsigned*)&sPh[(m + gid + 8) * SPP + kk + 8 + tig * 2];
            al[0] = *(unsigned*)&sPl[(m + gid) * SPP + kk + tig * 2];
            al[1] = *(unsigned*)&sPl[(m + gid + 8) * SPP + kk + tig * 2];
            al[2] = *(unsigned*)&sPl[(m + gid) * SPP + kk + 8 + tig * 2];
            al[3] = *(unsigned*)&sPl[(m + gid + 8) * SPP + kk + 8 + tig * 2];
#pragma unroll
            for (int nt = 0; nt < 4; nt++) {
                int n = wc * 32 + nt * 8 + gid;
                unsigned bh[2], bl[2];
                bh[0] = *(unsigned*)&sVh[n * SPP + kk + tig * 2];
                bh[1] = *(unsigned*)&sVh[n * SPP + kk + 8 + tig * 2];
                bl[0] = *(unsigned*)&sVl[n * SPP + kk + tig * 2];
                bl[1] = *(unsigned*)&sVl[n * SPP + kk + 8 + tig * 2];
                mma16816(acc2[nt], ah, bh);
                mma16816(acc2[nt], ah, bl);
                mma16816(acc2[nt], al, bh);
            }
        }
        __syncthreads();   // before next iteration overwrites K/P and V
    }

    // ---- rowsum reduce: over tig lanes, then across the 2 n-warps ----
    rs0 += __shfl_xor_sync(0xffffffffu, rs0, 1);
    rs0 += __shfl_xor_sync(0xffffffffu, rs0, 2);
    rs1 += __shfl_xor_sync(0xffffffffu, rs1, 1);
    rs1 += __shfl_xor_sync(0xffffffffu, rs1, 2);
    if (tig == 0) {
        atomicAdd(&rsum[m + gid], rs0);        // exactly 2 contributors: bit-exact
        atomicAdd(&rsum[m + gid + 8], rs1);
    }
    __syncthreads();

    if (tid < 64)
        g_inv[b * SEQ + m0 + tid] = 1.0f / rsum[tid];

    const int rr0 = m + gid, rr1 = rr0 + 8;
    const float iv0 = 1.0f / rsum[rr0];
    const float iv1 = 1.0f / rsum[rr1];
#pragma unroll
    for (int nt = 0; nt < 4; nt++) {
        int col = wc * 32 + nt * 8 + tig * 2;
        float2 v0 = { acc2[nt][0] * iv0, acc2[nt][1] * iv0 };
        float2 v1 = { acc2[nt][2] * iv1, acc2[nt][3] * iv1 };
        *(float2*)&attended[((size_t)b * SEQ + m0 + rr0) * DKK + col] = v0;
        *(float2*)&attended[((size_t)b * SEQ + m0 + rr1) * DKK + col] = v1;
    }
}

// ---------------------------------------------------------------------------
// Kernel 3: streaming normalize of weights: w[row][*] *= g_inv[row].
// One block per row; 2 float4 per thread.
// ---------------------------------------------------------------------------
__global__ void __launch_bounds__(256) norm_weights(float* __restrict__ weights) {
    const int row = blockIdx.x;                 // 0 .. BATCH*SEQ-1
    const float iv = g_inv[row];
    float4* w = (float4*)(weights + (size_t)row * SEQ);
    const int tid = threadIdx.x;
#pragma unroll
    for (int j = 0; j < 2; j++) {
        int i = tid + j * 256;
        float4 f = w[i];
        f.x *= iv; f.y *= iv; f.z *= iv; f.w *= iv;
        w[i] = f;
    }
}

// ---------------------------------------------------------------------------
extern "C" void kernel_launch(void* const* d_in, const int* in_sizes, int n_in,
                              void* d_out, int out_size) {
    const float* in = (const float*)d_in[0];
    const float* Wq = (const float*)d_in[1];
    const float* Wk = (const float*)d_in[2];
    const float* Wv = (const float*)d_in[3];

    float* out      = (float*)d_out;
    float* attended = out;                               // [B,S,DK]
    float* weights  = out + (size_t)BATCH * SEQ * DKK;   // [B,S,S]

    const int SMEM_BYTES = 45056 * 2 + 64 * 4;           // 90368
    cudaFuncSetAttribute(fused_attn, cudaFuncAttributeMaxDynamicSharedMemorySize, SMEM_BYTES);

    // 1) QKV projection
    dim3 g1(SEQ * BATCH / 128, 3);
    qkv_mma<<<g1, 256>>>(in, Wq, Wk, Wv);

    // 1b) transpose V
    dim3 gt(SEQ / 128, BATCH);
    vtrans<<<gt, 256>>>();

    // 2) fused attention: unnormalized weights + normalized attended + g_inv
    dim3 g2(SEQ / BM, BATCH);
    fused_attn<<<g2, 256, SMEM_BYTES>>>(weights, attended);

    // 3) normalize weights in place
    norm_weights<<<BATCH * SEQ, 256>>>(weights);
}